// round 2
// baseline (speedup 1.0000x reference)
#include <cuda_runtime.h>
#include <math.h>

#define NSMP   256000        // samples per batch = 2^11 * 5^3
#define NBATCH 4
#define NFR    500
#define NBK    64
#define NFQ    128001        // NSMP/2 + 1

// ---------------- scratch (static device globals; no allocation) ----------------
__device__ float2 g_bufA[2][NSMP];   // 4 MB
__device__ float2 g_bufB[2][NSMP];   // 4 MB
__device__ float  g_H[NBATCH][NFQ];  // 2 MB
__device__ float  g_w[NFR];
__device__ float  g_mm[NBATCH][NBK];

// ---------------- small helpers ----------------
__device__ __forceinline__ float2 c_add(float2 a, float2 b){ return make_float2(a.x+b.x, a.y+b.y); }
__device__ __forceinline__ float2 c_sub(float2 a, float2 b){ return make_float2(a.x-b.x, a.y-b.y); }

// ---------------- frame-mean weights (exact, deterministic) ----------------
__global__ void k_frame_w() {
    int f = blockIdx.x * blockDim.x + threadIdx.x;
    if (f >= NFR) return;
    const double s     = 499.0 / 255999.0;       // linspace step
    const double inv_s = 255999.0 / 499.0;
    int i0 = (int)((double)(f - 1) * inv_s) - 2; if (i0 < 0) i0 = 0;
    int i1 = (int)((double)(f + 1) * inv_s) + 2; if (i1 > NSMP - 1) i1 = NSMP - 1;
    double acc = 0.0;
    for (int i = i0; i <= i1; i++) {
        double pos = (double)i * s;
        int lo = (int)pos; if (lo > NFR - 2) lo = NFR - 2;
        double frac = pos - (double)lo;
        if (lo == f)          acc += 1.0 - frac;
        else if (lo == f - 1) acc += frac;
    }
    g_w[f] = (float)(acc / (double)NSMP);
}

// ---------------- mean magnitude per (batch, bank) ----------------
__global__ void k_mean_mag(const float* __restrict__ mag) {
    int t = threadIdx.x;           // 256 threads: b = t/64, k = t%64
    int b = t >> 6, k = t & 63;
    float acc = 0.f;
    for (int f = 0; f < NFR; f++)
        acc += g_w[f] * mag[(b * NFR + f) * NBK + k];
    g_mm[b][k] = acc;
}

// ---------------- filter response H[b][f] via geometric recurrence ----------------
__global__ void __launch_bounds__(256) k_filter_H() {
    __shared__ float smm[NBATCH][NBK];
    int tid = threadIdx.x;
    if (tid < NBATCH * NBK) smm[tid >> 6][tid & 63] = g_mm[tid >> 6][tid & 63];
    __syncthreads();

    int f = blockIdx.x * blockDim.x + tid;
    if (f >= NFQ) return;

    const float a = logf(20.0f);
    const float d = (logf(11025.0f) - a) / (float)(NBK - 1);

    float freq = (float)f * (22050.0f / (float)NSMP);
    float x  = logf(freq + 1e-7f);
    float xp = x - a;

    // term_k = exp(-2*(xp - k*d)^2);  term_{k+1} = term_k * r_k;  r_{k+1} = r_k * g
    float term = __expf(-2.0f * xp * xp);
    float r    = __expf(4.0f * xp * d - 2.0f * d * d);
    const float g = __expf(-4.0f * d * d);

    float sum = 0.f, a0 = 0.f, a1 = 0.f, a2 = 0.f, a3 = 0.f;
#pragma unroll
    for (int k = 0; k < NBK; k++) {
        sum += term;
        a0 += term * smm[0][k];
        a1 += term * smm[1][k];
        a2 += term * smm[2][k];
        a3 += term * smm[3][k];
        term *= r;
        r   *= g;
    }
    float inv = 1.0f / (sum + 1e-7f);
    g_H[0][f] = a0 * inv;
    g_H[1][f] = a1 * inv;
    g_H[2][f] = a2 * inv;
    g_H[3][f] = a3 * inv;
}

// ---------------- pack 4 real signals into 2 complex ----------------
__global__ void __launch_bounds__(256) k_pack(const float* __restrict__ noise) {
    int i = blockIdx.x * 256 + threadIdx.x;
    if (i >= NSMP) return;
    int s = blockIdx.y;
    g_bufA[s][i] = make_float2(noise[(2 * s) * NSMP + i], noise[(2 * s + 1) * NSMP + i]);
}

// ---------------- butterflies ----------------
template<int R, bool INV>
__device__ __forceinline__ void butterfly(float2* v) {
    const float s = INV ? 1.f : -1.f;
    if constexpr (R == 2) {
        float2 a = v[0], b = v[1];
        v[0] = c_add(a, b); v[1] = c_sub(a, b);
    } else if constexpr (R == 4) {
        float2 t0 = c_add(v[0], v[2]), t1 = c_sub(v[0], v[2]);
        float2 t2 = c_add(v[1], v[3]), t3 = c_sub(v[1], v[3]);
        float2 it3 = make_float2(-s * t3.y, s * t3.x);
        v[0] = c_add(t0, t2); v[2] = c_sub(t0, t2);
        v[1] = c_add(t1, it3); v[3] = c_sub(t1, it3);
    } else if constexpr (R == 5) {
        const float c1 = 0.30901699437494742f, c2 = -0.80901699437494745f;
        const float s1 = 0.95105651629515357f, s2 =  0.58778525229247312f;
        float2 t1 = c_add(v[1], v[4]), t2 = c_add(v[2], v[3]);
        float2 t3 = c_sub(v[1], v[4]), t4 = c_sub(v[2], v[3]);
        float2 x0 = v[0];
        float2 m1 = make_float2(x0.x + c1 * t1.x + c2 * t2.x, x0.y + c1 * t1.y + c2 * t2.y);
        float2 m2 = make_float2(x0.x + c2 * t1.x + c1 * t2.x, x0.y + c2 * t1.y + c1 * t2.y);
        float2 u1 = make_float2(s1 * t3.x + s2 * t4.x, s1 * t3.y + s2 * t4.y);
        float2 u2 = make_float2(s2 * t3.x - s1 * t4.x, s2 * t3.y - s1 * t4.y);
        float2 iu1 = make_float2(-s * u1.y, s * u1.x);
        float2 iu2 = make_float2(-s * u2.y, s * u2.x);
        v[0] = make_float2(x0.x + t1.x + t2.x, x0.y + t1.y + t2.y);
        v[1] = c_add(m1, iu1); v[4] = c_sub(m1, iu1);
        v[2] = c_add(m2, iu2); v[3] = c_sub(m2, iu2);
    }
}

// ---------------- Stockham stage ----------------
template<int R, int NS, bool INV, bool A2B>
__global__ void __launch_bounds__(256) k_stage() {
    constexpr int T = NSMP / R;
    int j = blockIdx.x * 256 + threadIdx.x;
    if (j >= T) return;
    const float2* __restrict__ x = A2B ? g_bufA[blockIdx.y] : g_bufB[blockIdx.y];
    float2*       __restrict__ y = A2B ? g_bufB[blockIdx.y] : g_bufA[blockIdx.y];

    int m = j % NS;
    float2 v[R];
#pragma unroll
    for (int r = 0; r < R; r++) v[r] = x[j + r * T];

    if constexpr (NS > 1) {
        const float sgn = INV ? 1.f : -1.f;
        float base = sgn * 6.283185307179586f * (float)m / (float)(NS * R);
#pragma unroll
        for (int r = 1; r < R; r++) {
            float sn, cs;
            sincosf(base * (float)r, &sn, &cs);
            float2 t = v[r];
            v[r] = make_float2(t.x * cs - t.y * sn, t.x * sn + t.y * cs);
        }
    }

    butterfly<R, INV>(v);

    int dbase = (j / NS) * (NS * R) + m;
#pragma unroll
    for (int r = 0; r < R; r++) y[dbase + r * NS] = v[r];
}

// ---------------- pointwise: un-pack pair spectra, apply H, re-pack ----------------
__global__ void __launch_bounds__(256) k_pointwise() {
    int k = blockIdx.x * 256 + threadIdx.x;
    if (k >= NSMP) return;
    int s = blockIdx.y;
    float2 zk = g_bufB[s][k];
    int nk = (k == 0) ? 0 : (NSMP - k);
    float2 zn = g_bufB[s][nk];
    // X0 = (Z_k + conj(Z_{N-k}))/2 ; X1 = (Z_k - conj(Z_{N-k}))/(2i)
    float X0r = 0.5f * (zk.x + zn.x), X0i = 0.5f * (zk.y - zn.y);
    float dxr = 0.5f * (zk.x - zn.x), dxi = 0.5f * (zk.y + zn.y);
    float X1r = dxi, X1i = -dxr;
    int kh = (k <= NSMP / 2) ? k : (NSMP - k);
    float h0 = g_H[2 * s][kh], h1 = g_H[2 * s + 1][kh];
    // W = h0*X0 + i*h1*X1
    g_bufA[s][k] = make_float2(h0 * X0r - h1 * X1i, h0 * X0i + h1 * X1r);
}

// ---------------- unpack + 1/N scale ----------------
__global__ void __launch_bounds__(256) k_unpack(float* __restrict__ out) {
    int i = blockIdx.x * 256 + threadIdx.x;
    if (i >= NSMP) return;
    int s = blockIdx.y;
    const float sc = 1.0f / (float)NSMP;
    float2 v = g_bufB[s][i];
    out[(2 * s) * NSMP + i]     = v.x * sc;
    out[(2 * s + 1) * NSMP + i] = v.y * sc;
}

// ---------------- launch ----------------
extern "C" void kernel_launch(void* const* d_in, const int* in_sizes, int n_in,
                              void* d_out, int out_size) {
    const float* mag;
    const float* noise;
    if (in_sizes[0] == NBATCH * NFR * NBK) { mag = (const float*)d_in[0]; noise = (const float*)d_in[1]; }
    else                                   { mag = (const float*)d_in[1]; noise = (const float*)d_in[0]; }
    float* out = (float*)d_out;

    k_frame_w<<<2, 256>>>();
    k_mean_mag<<<1, 256>>>(mag);
    k_filter_H<<<(NFQ + 255) / 256, 256>>>();

    dim3 gN((NSMP + 255) / 256, 2);
    k_pack<<<gN, 256>>>(noise);

    // forward FFT: radices 4,4,4,4,4,2,5,5,5  (Ns: 1,4,16,64,256,1024,2048,10240,51200)
    k_stage<4, 1,     false, true ><<<dim3(250, 2), 256>>>();
    k_stage<4, 4,     false, false><<<dim3(250, 2), 256>>>();
    k_stage<4, 16,    false, true ><<<dim3(250, 2), 256>>>();
    k_stage<4, 64,    false, false><<<dim3(250, 2), 256>>>();
    k_stage<4, 256,   false, true ><<<dim3(250, 2), 256>>>();
    k_stage<2, 1024,  false, false><<<dim3(500, 2), 256>>>();
    k_stage<5, 2048,  false, true ><<<dim3(200, 2), 256>>>();
    k_stage<5, 10240, false, false><<<dim3(200, 2), 256>>>();
    k_stage<5, 51200, false, true ><<<dim3(200, 2), 256>>>();   // spectrum in bufB

    k_pointwise<<<gN, 256>>>();                                  // bufB -> bufA

    // inverse FFT (same stage ladder, sign flipped)
    k_stage<4, 1,     true, true ><<<dim3(250, 2), 256>>>();
    k_stage<4, 4,     true, false><<<dim3(250, 2), 256>>>();
    k_stage<4, 16,    true, true ><<<dim3(250, 2), 256>>>();
    k_stage<4, 64,    true, false><<<dim3(250, 2), 256>>>();
    k_stage<4, 256,   true, true ><<<dim3(250, 2), 256>>>();
    k_stage<2, 1024,  true, false><<<dim3(500, 2), 256>>>();
    k_stage<5, 2048,  true, true ><<<dim3(200, 2), 256>>>();
    k_stage<5, 10240, true, false><<<dim3(200, 2), 256>>>();
    k_stage<5, 51200, true, true ><<<dim3(200, 2), 256>>>();    // time domain in bufB

    k_unpack<<<gN, 256>>>(out);
}

// round 3
// speedup vs baseline: 14.1594x; 14.1594x over previous
#include <cuda_runtime.h>
#include <math.h>

#define NSMP   256000        // 2^11 * 5^3
#define NBATCH 4
#define NFR    500
#define NBK    64
#define NFQ    128001        // NSMP/2 + 1

// ---------------- scratch ----------------
__device__ float2 g_bufA[2][NSMP];   // 4 MB
__device__ float2 g_bufB[2][NSMP];   // 4 MB
__device__ float  g_H[NBATCH][NFQ];  // 2 MB
__device__ float  g_w[NFR];
__device__ float  g_mm[NBATCH][NBK];
__device__ float2 g_tw16c[16];
__device__ float2 g_tw8c[8];
__device__ float2 g_tw25c[25];

// ---------------- helpers ----------------
__device__ __forceinline__ float2 c_add(float2 a, float2 b){ return make_float2(a.x+b.x, a.y+b.y); }
__device__ __forceinline__ float2 c_sub(float2 a, float2 b){ return make_float2(a.x-b.x, a.y-b.y); }

template<bool INV>
__device__ __forceinline__ float2 twc_mul(float2 z, float2 w) {
    // w = (cos, sin) of +angle; forward uses conj
    float wi = INV ? w.y : -w.y;
    return make_float2(z.x*w.x - z.y*wi, z.x*wi + z.y*w.x);
}

// ---------------- constant twiddle tables (init once, double precision) ----------------
__global__ void k_init_tw() {
    int t = threadIdx.x;
    const double TWO_PI = 6.283185307179586476925286766559;
    if (t < 16) { double a = TWO_PI/16.0*(double)t; g_tw16c[t] = make_float2((float)cos(a),(float)sin(a)); }
    if (t < 8)  { double a = TWO_PI/8.0 *(double)t; g_tw8c[t]  = make_float2((float)cos(a),(float)sin(a)); }
    if (t < 25) { double a = TWO_PI/25.0*(double)t; g_tw25c[t] = make_float2((float)cos(a),(float)sin(a)); }
}

// ---------------- frame-mean weights (parallel, deterministic) ----------------
__global__ void k_frame_w() {
    int f = blockIdx.x;
    const double s     = 499.0 / 255999.0;
    const double inv_s = 255999.0 / 499.0;
    int i0 = (int)((double)(f - 1) * inv_s) - 2; if (i0 < 0) i0 = 0;
    int i1 = (int)((double)(f + 1) * inv_s) + 2; if (i1 > NSMP - 1) i1 = NSMP - 1;
    double acc = 0.0;
    for (int i = i0 + (int)threadIdx.x; i <= i1; i += 256) {
        double pos = (double)i * s;
        int lo = (int)pos; if (lo > NFR - 2) lo = NFR - 2;
        double frac = pos - (double)lo;
        if (lo == f)          acc += 1.0 - frac;
        else if (lo == f - 1) acc += frac;
    }
    __shared__ double sh[256];
    sh[threadIdx.x] = acc; __syncthreads();
    for (int o = 128; o > 0; o >>= 1) {
        if ((int)threadIdx.x < o) sh[threadIdx.x] += sh[threadIdx.x + o];
        __syncthreads();
    }
    if (threadIdx.x == 0) g_w[f] = (float)(sh[0] / (double)NSMP);
}

// ---------------- mean magnitude per (batch, bank) ----------------
__global__ void k_mean_mag(const float* __restrict__ mag) {
    int t = threadIdx.x;
    int b = t >> 6, k = t & 63;
    float acc = 0.f;
    for (int f = 0; f < NFR; f++)
        acc += g_w[f] * mag[(b * NFR + f) * NBK + k];
    g_mm[b][k] = acc;
}

// ---------------- filter response H[b][f] ----------------
__global__ void __launch_bounds__(256) k_filter_H() {
    __shared__ float smm[NBATCH][NBK];
    int tid = threadIdx.x;
    if (tid < NBATCH * NBK) smm[tid >> 6][tid & 63] = g_mm[tid >> 6][tid & 63];
    __syncthreads();

    int f = blockIdx.x * blockDim.x + tid;
    if (f >= NFQ) return;

    const float a = logf(20.0f);
    const float d = (logf(11025.0f) - a) / (float)(NBK - 1);

    float freq = (float)f * (22050.0f / (float)NSMP);
    float x  = logf(freq + 1e-7f);
    float xp = x - a;

    float term = __expf(-2.0f * xp * xp);
    float r    = __expf(4.0f * xp * d - 2.0f * d * d);
    const float g = __expf(-4.0f * d * d);

    float sum = 0.f, a0 = 0.f, a1 = 0.f, a2 = 0.f, a3 = 0.f;
#pragma unroll
    for (int k = 0; k < NBK; k++) {
        sum += term;
        a0 += term * smm[0][k];
        a1 += term * smm[1][k];
        a2 += term * smm[2][k];
        a3 += term * smm[3][k];
        term *= r;
        r   *= g;
    }
    float inv = 1.0f / (sum + 1e-7f);
    g_H[0][f] = a0 * inv;
    g_H[1][f] = a1 * inv;
    g_H[2][f] = a2 * inv;
    g_H[3][f] = a3 * inv;
}

// ---------------- small butterflies ----------------
template<int R, bool INV>
__device__ __forceinline__ void butterfly(float2* v) {
    const float s = INV ? 1.f : -1.f;
    if constexpr (R == 2) {
        float2 a = v[0], b = v[1];
        v[0] = c_add(a, b); v[1] = c_sub(a, b);
    } else if constexpr (R == 4) {
        float2 t0 = c_add(v[0], v[2]), t1 = c_sub(v[0], v[2]);
        float2 t2 = c_add(v[1], v[3]), t3 = c_sub(v[1], v[3]);
        float2 it3 = make_float2(-s * t3.y, s * t3.x);
        v[0] = c_add(t0, t2); v[2] = c_sub(t0, t2);
        v[1] = c_add(t1, it3); v[3] = c_sub(t1, it3);
    } else if constexpr (R == 5) {
        const float c1 = 0.30901699437494742f, c2 = -0.80901699437494745f;
        const float s1 = 0.95105651629515357f, s2 =  0.58778525229247312f;
        float2 t1 = c_add(v[1], v[4]), t2 = c_add(v[2], v[3]);
        float2 t3 = c_sub(v[1], v[4]), t4 = c_sub(v[2], v[3]);
        float2 x0 = v[0];
        float2 m1 = make_float2(x0.x + c1 * t1.x + c2 * t2.x, x0.y + c1 * t1.y + c2 * t2.y);
        float2 m2 = make_float2(x0.x + c2 * t1.x + c1 * t2.x, x0.y + c2 * t1.y + c1 * t2.y);
        float2 u1 = make_float2(s1 * t3.x + s2 * t4.x, s1 * t3.y + s2 * t4.y);
        float2 u2 = make_float2(s2 * t3.x - s1 * t4.x, s2 * t3.y - s1 * t4.y);
        float2 iu1 = make_float2(-s * u1.y, s * u1.x);
        float2 iu2 = make_float2(-s * u2.y, s * u2.x);
        v[0] = make_float2(x0.x + t1.x + t2.x, x0.y + t1.y + t2.y);
        v[1] = c_add(m1, iu1); v[4] = c_sub(m1, iu1);
        v[2] = c_add(m2, iu2); v[3] = c_sub(m2, iu2);
    }
}

// ---------------- composite butterflies (natural-order DFTs) ----------------
template<bool INV>
__device__ __forceinline__ void butterfly16(float2* v) {
    float2 u[16];
#pragma unroll
    for (int b = 0; b < 4; b++) {
        float2 y[4] = { v[b], v[b+4], v[b+8], v[b+12] };
        butterfly<4, INV>(y);
#pragma unroll
        for (int c = 0; c < 4; c++) u[b*4 + c] = y[c];
    }
#pragma unroll
    for (int b = 1; b < 4; b++)
#pragma unroll
        for (int c = 1; c < 4; c++)
            u[b*4 + c] = twc_mul<INV>(u[b*4 + c], g_tw16c[b*c]);
#pragma unroll
    for (int c = 0; c < 4; c++) {
        float2 y[4] = { u[c], u[4+c], u[8+c], u[12+c] };
        butterfly<4, INV>(y);
#pragma unroll
        for (int d = 0; d < 4; d++) v[c + 4*d] = y[d];
    }
}

template<bool INV>
__device__ __forceinline__ void butterfly8(float2* v) {
    float2 u0[4] = { v[0], v[2], v[4], v[6] };
    float2 u1[4] = { v[1], v[3], v[5], v[7] };
    butterfly<4, INV>(u0);
    butterfly<4, INV>(u1);
#pragma unroll
    for (int c = 0; c < 4; c++) {
        float2 t = (c == 0) ? u1[0] : twc_mul<INV>(u1[c], g_tw8c[c]);
        v[c]     = c_add(u0[c], t);
        v[c + 4] = c_sub(u0[c], t);
    }
}

template<bool INV>
__device__ __forceinline__ void butterfly25(float2* v) {
    float2 u[25];
#pragma unroll
    for (int b = 0; b < 5; b++) {
        float2 y[5] = { v[b], v[b+5], v[b+10], v[b+15], v[b+20] };
        butterfly<5, INV>(y);
#pragma unroll
        for (int c = 0; c < 5; c++) u[b*5 + c] = y[c];
    }
#pragma unroll
    for (int b = 1; b < 5; b++)
#pragma unroll
        for (int c = 1; c < 5; c++)
            u[b*5 + c] = twc_mul<INV>(u[b*5 + c], g_tw25c[b*c]);
#pragma unroll
    for (int c = 0; c < 5; c++) {
        float2 y[5] = { u[c], u[5+c], u[10+c], u[15+c], u[20+c] };
        butterfly<5, INV>(y);
#pragma unroll
        for (int d = 0; d < 5; d++) v[c + 5*d] = y[d];
    }
}

template<int R, bool INV>
__device__ __forceinline__ void bfly(float2* v) {
    if constexpr (R == 16)      butterfly16<INV>(v);
    else if constexpr (R == 8)  butterfly8<INV>(v);
    else if constexpr (R == 25) butterfly25<INV>(v);
    else                        butterfly<R, INV>(v);
}

// ---------------- generic Stockham stage ----------------
template<int R, int NS, bool INV, bool A2B>
__global__ void __launch_bounds__(256) k_stage() {
    constexpr int T = NSMP / R;
    int j = blockIdx.x * 256 + threadIdx.x;
    if (j >= T) return;
    const float2* __restrict__ x = A2B ? g_bufA[blockIdx.y] : g_bufB[blockIdx.y];
    float2*       __restrict__ y = A2B ? g_bufB[blockIdx.y] : g_bufA[blockIdx.y];

    int m = j % NS;
    float2 v[R];
#pragma unroll
    for (int r = 0; r < R; r++) v[r] = x[j + r * T];

    if constexpr (NS > 1) {
        const float sgn = INV ? 1.f : -1.f;
        float base = sgn * 6.2831853071795864f / (float)(NS * R) * (float)m;
#pragma unroll
        for (int r = 1; r < R; r++) {
            float sn, cs;
            __sincosf(base * (float)r, &sn, &cs);
            float2 t = v[r];
            v[r] = make_float2(t.x * cs - t.y * sn, t.x * sn + t.y * cs);
        }
    }

    bfly<R, INV>(v);

    int dbase = (j / NS) * (NS * R) + m;
#pragma unroll
    for (int r = 0; r < R; r++) y[dbase + r * NS] = v[r];
}

// ---------------- forward stage 1: radix-16, NS=1, fused pack ----------------
__global__ void __launch_bounds__(256) k_s1f(const float* __restrict__ noise) {
    constexpr int T = NSMP / 16;
    int j = blockIdx.x * 256 + threadIdx.x;
    if (j >= T) return;
    int s = blockIdx.y;
    const float* __restrict__ n0 = noise + (2 * s) * NSMP;
    const float* __restrict__ n1 = noise + (2 * s + 1) * NSMP;
    float2 v[16];
#pragma unroll
    for (int r = 0; r < 16; r++) v[r] = make_float2(n0[j + r * T], n1[j + r * T]);
    bfly<16, false>(v);
    float2* __restrict__ y = g_bufA[s];
#pragma unroll
    for (int r = 0; r < 16; r++) y[j * 16 + r] = v[r];
}

// ---------------- inverse stage 1: radix-16, NS=1, fused spectral filter ----------------
__global__ void __launch_bounds__(256) k_s1i() {
    constexpr int T = NSMP / 16;
    int j = blockIdx.x * 256 + threadIdx.x;
    if (j >= T) return;
    int s = blockIdx.y;
    const float2* __restrict__ Z = g_bufA[s];
    const float* __restrict__ H0 = g_H[2 * s];
    const float* __restrict__ H1 = g_H[2 * s + 1];
    float2 v[16];
#pragma unroll
    for (int r = 0; r < 16; r++) {
        int k = j + r * T;
        float2 zk = Z[k];
        float2 zn = Z[k ? NSMP - k : 0];
        // X0 = (Z_k + conj(Z_{N-k}))/2 ; X1 = (Z_k - conj(Z_{N-k}))/(2i)
        float X0r = 0.5f * (zk.x + zn.x), X0i = 0.5f * (zk.y - zn.y);
        float X1r = 0.5f * (zk.y + zn.y), X1i = -0.5f * (zk.x - zn.x);
        int kh = (k <= NSMP / 2) ? k : NSMP - k;
        float h0 = H0[kh], h1 = H1[kh];
        // W = h0*X0 + i*h1*X1
        v[r] = make_float2(h0 * X0r - h1 * X1i, h0 * X0i + h1 * X1r);
    }
    bfly<16, true>(v);
    float2* __restrict__ y = g_bufB[s];
#pragma unroll
    for (int r = 0; r < 16; r++) y[j * 16 + r] = v[r];
}

// ---------------- inverse stage 5: radix-5, NS=51200, fused unpack + scale ----------------
__global__ void __launch_bounds__(256) k_s5i(float* __restrict__ out) {
    constexpr int NS = 51200, T = NSMP / 5;
    int j = blockIdx.x * 256 + threadIdx.x;
    if (j >= T) return;
    int s = blockIdx.y;
    const float2* __restrict__ x = g_bufA[s];
    float2 v[5];
#pragma unroll
    for (int r = 0; r < 5; r++) v[r] = x[j + r * T];

    float base = 6.2831853071795864f / (float)NSMP * (float)j;  // inverse: +sign
#pragma unroll
    for (int r = 1; r < 5; r++) {
        float sn, cs;
        __sincosf(base * (float)r, &sn, &cs);
        float2 t = v[r];
        v[r] = make_float2(t.x * cs - t.y * sn, t.x * sn + t.y * cs);
    }
    bfly<5, true>(v);

    const float sc = 1.0f / (float)NSMP;
    float* __restrict__ o0 = out + (2 * s) * NSMP;
    float* __restrict__ o1 = out + (2 * s + 1) * NSMP;
#pragma unroll
    for (int r = 0; r < 5; r++) {
        int idx = j + r * NS;
        o0[idx] = v[r].x * sc;
        o1[idx] = v[r].y * sc;
    }
}

// ---------------- launch ----------------
extern "C" void kernel_launch(void* const* d_in, const int* in_sizes, int n_in,
                              void* d_out, int out_size) {
    const float* mag;
    const float* noise;
    if (in_sizes[0] == NBATCH * NFR * NBK) { mag = (const float*)d_in[0]; noise = (const float*)d_in[1]; }
    else                                   { mag = (const float*)d_in[1]; noise = (const float*)d_in[0]; }
    float* out = (float*)d_out;

    k_init_tw<<<1, 32>>>();
    k_frame_w<<<NFR, 256>>>();
    k_mean_mag<<<1, 256>>>(mag);
    k_filter_H<<<(NFQ + 255) / 256, 256>>>();

    dim3 g16(63, 2), g8(125, 2), g25(40, 2), g5(200, 2);

    // forward FFT: radices 16,16,8,25,5 (Ns = 1,16,256,2048,51200)
    k_s1f<<<g16, 256>>>(noise);                          // noise -> A
    k_stage<16, 16,   false, true ><<<g16, 256>>>();     // A -> B
    k_stage<8,  256,  false, false><<<g8,  256>>>();     // B -> A
    k_stage<25, 2048, false, true ><<<g25, 256>>>();     // A -> B
    k_stage<5,  51200,false, false><<<g5,  256>>>();     // B -> A  (spectrum in A)

    // inverse FFT with fused spectral filter + fused output
    k_s1i<<<g16, 256>>>();                               // A -> B  (filter fused)
    k_stage<16, 16,   true, false><<<g16, 256>>>();      // B -> A
    k_stage<8,  256,  true, true ><<<g8,  256>>>();      // A -> B
    k_stage<25, 2048, true, false><<<g25, 256>>>();      // B -> A
    k_s5i<<<g5, 256>>>(out);                             // A -> out (scale fused)
}

// round 4
// speedup vs baseline: 30.2969x; 2.1397x over previous
#include <cuda_runtime.h>
#include <math.h>

#define NSMP   256000        // = 512 * 500
#define N1     512
#define N2     500
#define NBATCH 4
#define NFR    500
#define NBK    64
#define NFQ    128001
#define NCH    10            // frame chunks
#define CHF    50            // frames per chunk

// ---------------- scratch ----------------
__device__ float2 g_u[2][N1 * N2];     // pass1 fwd out / passA inv out
__device__ float2 g_S[2][N1 * N2];     // spectrum (k1-major)
__device__ float  g_H[NBATCH][NFQ];
__device__ float  g_part[NCH][NBATCH][NBK];

// ---------------- helpers ----------------
__device__ __forceinline__ float2 c_add(float2 a, float2 b){ return make_float2(a.x+b.x, a.y+b.y); }
__device__ __forceinline__ float2 c_sub(float2 a, float2 b){ return make_float2(a.x-b.x, a.y-b.y); }
__device__ __forceinline__ float2 cmul(float2 z, float cs, float sn) {
    return make_float2(z.x*cs - z.y*sn, z.x*sn + z.y*cs);
}

template<int R, bool INV>
__device__ __forceinline__ void butterfly(float2* v) {
    const float s = INV ? 1.f : -1.f;
    if constexpr (R == 4) {
        float2 t0 = c_add(v[0], v[2]), t1 = c_sub(v[0], v[2]);
        float2 t2 = c_add(v[1], v[3]), t3 = c_sub(v[1], v[3]);
        float2 it3 = make_float2(-s * t3.y, s * t3.x);
        v[0] = c_add(t0, t2); v[2] = c_sub(t0, t2);
        v[1] = c_add(t1, it3); v[3] = c_sub(t1, it3);
    } else if constexpr (R == 5) {
        const float c1 = 0.30901699437494742f, c2 = -0.80901699437494745f;
        const float s1 = 0.95105651629515357f, s2 =  0.58778525229247312f;
        float2 t1 = c_add(v[1], v[4]), t2 = c_add(v[2], v[3]);
        float2 t3 = c_sub(v[1], v[4]), t4 = c_sub(v[2], v[3]);
        float2 x0 = v[0];
        float2 m1 = make_float2(x0.x + c1*t1.x + c2*t2.x, x0.y + c1*t1.y + c2*t2.y);
        float2 m2 = make_float2(x0.x + c2*t1.x + c1*t2.x, x0.y + c2*t1.y + c1*t2.y);
        float2 u1 = make_float2(s1*t3.x + s2*t4.x, s1*t3.y + s2*t4.y);
        float2 u2 = make_float2(s2*t3.x - s1*t4.x, s2*t3.y - s1*t4.y);
        float2 iu1 = make_float2(-s*u1.y, s*u1.x);
        float2 iu2 = make_float2(-s*u2.y, s*u2.x);
        v[0] = make_float2(x0.x + t1.x + t2.x, x0.y + t1.y + t2.y);
        v[1] = c_add(m1, iu1); v[4] = c_sub(m1, iu1);
        v[2] = c_add(m2, iu2); v[3] = c_sub(m2, iu2);
    }
}

// radix-8 DIT: u0 = DFT4(even), u1 = DFT4(odd), combine with const twiddles
template<bool INV>
__device__ __forceinline__ void bfly8(float2* v) {
    float2 u0[4] = { v[0], v[2], v[4], v[6] };
    float2 u1[4] = { v[1], v[3], v[5], v[7] };
    butterfly<4, INV>(u0);
    butterfly<4, INV>(u1);
    const float h  = 0.70710678118654752f;
    const float si = INV ? 1.f : -1.f;
    float2 t0 = u1[0];
    float2 t1 = make_float2(h*(u1[1].x - si*u1[1].y), h*(si*u1[1].x + u1[1].y));
    float2 t2 = make_float2(-si*u1[2].y, si*u1[2].x);
    float2 t3 = make_float2(h*(-u1[3].x - si*u1[3].y), h*(si*u1[3].x - u1[3].y));
    v[0] = c_add(u0[0], t0); v[4] = c_sub(u0[0], t0);
    v[1] = c_add(u0[1], t1); v[5] = c_sub(u0[1], t1);
    v[2] = c_add(u0[2], t2); v[6] = c_sub(u0[2], t2);
    v[3] = c_add(u0[3], t3); v[7] = c_sub(u0[3], t3);
}

// ---------------- FFT-500 in shared memory (Stockham 4*5*5*5), natural->natural ----------------
template<bool INV>
__device__ __forceinline__ void fft500(float2* R, int t) {
    const float sg = INV ? 6.2831853071795864f : -6.2831853071795864f;
    {   // stage 1: radix 4, Ns=1, T=125
        float2 v[4];
        if (t < 125) {
#pragma unroll
            for (int r = 0; r < 4; r++) v[r] = R[t + 125*r];
            butterfly<4, INV>(v);
        }
        __syncthreads();
        if (t < 125) {
#pragma unroll
            for (int r = 0; r < 4; r++) R[t*4 + r] = v[r];
        }
        __syncthreads();
    }
    {   // stage 2: radix 5, Ns=4, T=100
        float2 v[5]; int m = t & 3;
        if (t < 100) {
#pragma unroll
            for (int r = 0; r < 5; r++) v[r] = R[t + 100*r];
            float base = sg / 20.f * (float)m;
#pragma unroll
            for (int r = 1; r < 5; r++) { float sn, cs; __sincosf(base*r, &sn, &cs); v[r] = cmul(v[r], cs, sn); }
            butterfly<5, INV>(v);
        }
        __syncthreads();
        if (t < 100) {
            int db = (t >> 2)*20 + m;
#pragma unroll
            for (int r = 0; r < 5; r++) R[db + 4*r] = v[r];
        }
        __syncthreads();
    }
    {   // stage 3: radix 5, Ns=20, T=100
        float2 v[5]; int m = t % 20;
        if (t < 100) {
#pragma unroll
            for (int r = 0; r < 5; r++) v[r] = R[t + 100*r];
            float base = sg / 100.f * (float)m;
#pragma unroll
            for (int r = 1; r < 5; r++) { float sn, cs; __sincosf(base*r, &sn, &cs); v[r] = cmul(v[r], cs, sn); }
            butterfly<5, INV>(v);
        }
        __syncthreads();
        if (t < 100) {
            int db = (t/20)*100 + m;
#pragma unroll
            for (int r = 0; r < 5; r++) R[db + 20*r] = v[r];
        }
        __syncthreads();
    }
    {   // stage 4: radix 5, Ns=100, T=100
        float2 v[5];
        if (t < 100) {
#pragma unroll
            for (int r = 0; r < 5; r++) v[r] = R[t + 100*r];
            float base = sg / 500.f * (float)t;
#pragma unroll
            for (int r = 1; r < 5; r++) { float sn, cs; __sincosf(base*r, &sn, &cs); v[r] = cmul(v[r], cs, sn); }
            butterfly<5, INV>(v);
        }
        __syncthreads();
        if (t < 100) {
#pragma unroll
            for (int r = 0; r < 5; r++) R[t + 100*r] = v[r];
        }
        __syncthreads();
    }
}

// ---------------- partial mean-magnitude with inline closed-form frame weights ----------------
__global__ void k_mm_part(const float* __restrict__ mag) {
    int c = blockIdx.x, b = blockIdx.y;
    int t = threadIdx.x;    // 64
    __shared__ float sw[CHF];
    if (t < CHF) {
        int f = c*CHF + t;
        const double s = 499.0/255999.0;
        long long a1 = ((long long)f*255999LL + 498LL)/499LL;            // ceil(f/s)
        long long b1 = ((long long)(f+1)*255999LL + 498LL)/499LL - 1LL;  // ceil((f+1)/s)-1
        if (b1 > 255999LL) b1 = 255999LL;
        double cnt1 = (double)(b1 - a1 + 1);
        double si1  = 0.5*(double)(a1 + b1)*cnt1;
        double sum  = cnt1*(double)(1 + f) - s*si1;
        if (f >= 1) {
            long long a2 = ((long long)(f-1)*255999LL + 498LL)/499LL;
            long long b2 = a1 - 1LL;
            if (b2 >= a2) {
                double cnt2 = (double)(b2 - a2 + 1);
                double si2  = 0.5*(double)(a2 + b2)*cnt2;
                sum += s*si2 - (double)(f-1)*cnt2;
            }
        }
        sw[t] = (float)(sum/256000.0);
    }
    __syncthreads();
    float acc = 0.f;
    const float* mp = mag + (b*NFR + c*CHF)*NBK + t;
#pragma unroll 10
    for (int f = 0; f < CHF; f++) acc += sw[f]*mp[f*NBK];
    g_part[c][b][t] = acc;
}

// ---------------- filter response H[b][f]; even/odd recurrence chains ----------------
__global__ void __launch_bounds__(128) k_filter_H() {
    __shared__ float smm[NBATCH*NBK];
    int t = threadIdx.x;
    for (int i = t; i < NBATCH*NBK; i += 128) {
        float a = 0.f;
        const float* p = (const float*)g_part;
#pragma unroll
        for (int c = 0; c < NCH; c++) a += p[c*256 + i];
        smm[i] = a;
    }
    __syncthreads();

    int f = blockIdx.x*128 + t;
    if (f >= NFQ) return;

    const float la = logf(20.0f);
    const float d  = (logf(11025.0f) - la)/63.f;
    float freq = (float)f * (22050.0f/256000.0f);
    float xp = logf(freq + 1e-7f) - la;

    float te = __expf(-2.f*xp*xp);
    float to = te * __expf(4.f*d*xp - 2.f*d*d);
    float Re = __expf(8.f*d*xp - 8.f*d*d);
    float Ro = Re * __expf(-8.f*d*d);
    const float g4 = __expf(-16.f*d*d);

    float sum = 0.f, a0 = 0.f, a1 = 0.f, a2 = 0.f, a3 = 0.f;
#pragma unroll
    for (int k = 0; k < 64; k += 2) {
        sum += te + to;
        a0 += te*smm[k]       + to*smm[k+1];
        a1 += te*smm[64+k]    + to*smm[65+k];
        a2 += te*smm[128+k]   + to*smm[129+k];
        a3 += te*smm[192+k]   + to*smm[193+k];
        te *= Re; Re *= g4;
        to *= Ro; Ro *= g4;
    }
    float inv = 1.f/(sum + 1e-7f);
    g_H[0][f] = a0*inv; g_H[1][f] = a1*inv;
    g_H[2][f] = a2*inv; g_H[3][f] = a3*inv;
}

// ---------------- forward pass 1: FFT-512 per column + cross twiddle (pack fused) ----------------
__global__ void __launch_bounds__(256) k_p1f(const float* __restrict__ noise) {
    __shared__ float2 sm[4][516];
    int tid = threadIdx.x;
    int c = tid & 3, j = tid >> 2;           // j in [0,64)
    int n2 = blockIdx.x*4 + c;
    int s = blockIdx.y;
    const float* n0r = noise + 2*s*NSMP;
    const float* n1r = noise + (2*s+1)*NSMP;

    float2 v[8];
#pragma unroll
    for (int r = 0; r < 8; r++) {
        int idx = (j + 64*r)*N2 + n2;
        v[r] = make_float2(n0r[idx], n1r[idx]);
    }
    // stage 1: Ns=1
    bfly8<false>(v);
#pragma unroll
    for (int r = 0; r < 8; r++) sm[c][j*8 + r] = v[r];
    __syncthreads();
#pragma unroll
    for (int r = 0; r < 8; r++) v[r] = sm[c][j + 64*r];
    __syncthreads();
    // stage 2: Ns=8
    {
        int m = j & 7;
        float base = -6.2831853071795864f/64.f * (float)m;
#pragma unroll
        for (int r = 1; r < 8; r++) { float sn, cs; __sincosf(base*r, &sn, &cs); v[r] = cmul(v[r], cs, sn); }
        bfly8<false>(v);
        int db = (j >> 3)*64 + m;
#pragma unroll
        for (int r = 0; r < 8; r++) sm[c][db + 8*r] = v[r];
    }
    __syncthreads();
#pragma unroll
    for (int r = 0; r < 8; r++) v[r] = sm[c][j + 64*r];
    // stage 3: Ns=64, then cross twiddle e^{-2pi i k1 n2 / N}, store u[k1][n2]
    {
        float base = -6.2831853071795864f/512.f * (float)j;
#pragma unroll
        for (int r = 1; r < 8; r++) { float sn, cs; __sincosf(base*r, &sn, &cs); v[r] = cmul(v[r], cs, sn); }
        bfly8<false>(v);
        float cb = -6.2831853071795864f/256000.f * (float)n2;
        float2* u = g_u[s];
#pragma unroll
        for (int r = 0; r < 8; r++) {
            int k1 = j + 64*r;
            float sn, cs; __sincosf(cb*(float)k1, &sn, &cs);
            u[k1*N2 + n2] = cmul(v[r], cs, sn);
        }
    }
}

// ---------------- forward pass 2: FFT-500 per k1-row ----------------
__global__ void __launch_bounds__(256) k_p2f() {
    __shared__ float2 sm[2][512];
    int tid = threadIdx.x;
    int row = tid >> 7, t = tid & 127;
    int k1 = blockIdx.x*2 + row;
    int s = blockIdx.y;
    float2* R = sm[row];
    const float2* u = g_u[s] + k1*N2;
    for (int i = t; i < N2; i += 128) R[i] = u[i];
    __syncthreads();
    fft500<false>(R, t);
    float2* Sx = g_S[s] + k1*N2;
    for (int i = t; i < N2; i += 128) Sx[i] = R[i];
}

// ---------------- inverse pass A: spectral filter (conjugate row-pairs) + iFFT-500 + twiddle ----------------
__global__ void __launch_bounds__(256) k_pAi() {
    __shared__ float2 smA[512], smB[512];
    int tid = threadIdx.x;
    int half = tid >> 7, t = tid & 127;
    int p = blockIdx.x;                  // 0..255
    int s = blockIdx.y;
    int ra = (p == 0) ? 0   : p;
    int rb = (p == 0) ? 256 : 512 - p;
    const float2* Ss = g_S[s];
    {
        int rr = half ? rb : ra;
        float2* dst = half ? smB : smA;
        const float2* src = Ss + rr*N2;
        for (int i = t; i < N2; i += 128) dst[i] = src[i];
    }
    __syncthreads();

    const float* H0 = g_H[2*s];
    const float* H1 = g_H[2*s + 1];
    int myrow = half ? rb : ra;
    float2* mysm = half ? smB : smA;
    float2 wv[4];
#pragma unroll
    for (int q = 0; q < 4; q++) {
        int k2 = t + q*128;
        if (k2 < N2) {
            float2 zk = mysm[k2];
            float2 zn;
            if (p == 0) {
                if (!half) zn = smA[k2 ? N2 - k2 : 0];     // row 0 self-paired
                else       zn = smB[N2 - 1 - k2];          // row 256 self-paired
            } else {
                zn = (half ? smA : smB)[N2 - 1 - k2];      // cross pair (k1 <-> 512-k1)
            }
            int k  = myrow + (k2 << 9);                    // k1 + 512*k2
            int kh = (k <= 128000) ? k : 256000 - k;
            float h0 = H0[kh], h1 = H1[kh];
            float X0r = 0.5f*(zk.x + zn.x), X0i = 0.5f*(zk.y - zn.y);
            float X1r = 0.5f*(zk.y + zn.y), X1i = -0.5f*(zk.x - zn.x);
            wv[q] = make_float2(h0*X0r - h1*X1i, h0*X0i + h1*X1r);
        }
    }
    __syncthreads();
#pragma unroll
    for (int q = 0; q < 4; q++) { int k2 = t + q*128; if (k2 < N2) mysm[k2] = wv[q]; }
    __syncthreads();

    fft500<true>(mysm, t);

    float cb = 6.2831853071795864f/256000.f * (float)myrow;
    float2* dst = g_u[s] + myrow*N2;
    for (int i = t; i < N2; i += 128) {
        float sn, cs; __sincosf(cb*(float)i, &sn, &cs);
        dst[i] = cmul(mysm[i], cs, sn);
    }
}

// ---------------- inverse pass B: iFFT-512 per column + scale + unpack to out ----------------
__global__ void __launch_bounds__(256) k_pBi(float* __restrict__ out) {
    __shared__ float2 sm[4][516];
    int tid = threadIdx.x;
    int c = tid & 3, j = tid >> 2;
    int n2 = blockIdx.x*4 + c;
    int s = blockIdx.y;
    const float2* u = g_u[s];

    float2 v[8];
#pragma unroll
    for (int r = 0; r < 8; r++) v[r] = u[(j + 64*r)*N2 + n2];
    // stage 1
    bfly8<true>(v);
#pragma unroll
    for (int r = 0; r < 8; r++) sm[c][j*8 + r] = v[r];
    __syncthreads();
#pragma unroll
    for (int r = 0; r < 8; r++) v[r] = sm[c][j + 64*r];
    __syncthreads();
    // stage 2
    {
        int m = j & 7;
        float base = 6.2831853071795864f/64.f * (float)m;
#pragma unroll
        for (int r = 1; r < 8; r++) { float sn, cs; __sincosf(base*r, &sn, &cs); v[r] = cmul(v[r], cs, sn); }
        bfly8<true>(v);
        int db = (j >> 3)*64 + m;
#pragma unroll
        for (int r = 0; r < 8; r++) sm[c][db + 8*r] = v[r];
    }
    __syncthreads();
#pragma unroll
    for (int r = 0; r < 8; r++) v[r] = sm[c][j + 64*r];
    // stage 3 + scale + unpack
    {
        float base = 6.2831853071795864f/512.f * (float)j;
#pragma unroll
        for (int r = 1; r < 8; r++) { float sn, cs; __sincosf(base*r, &sn, &cs); v[r] = cmul(v[r], cs, sn); }
        bfly8<true>(v);
        const float sc = 1.f/256000.f;
        float* o0 = out + 2*s*NSMP;
        float* o1 = out + (2*s+1)*NSMP;
#pragma unroll
        for (int r = 0; r < 8; r++) {
            int idx = (j + 64*r)*N2 + n2;
            o0[idx] = v[r].x * sc;
            o1[idx] = v[r].y * sc;
        }
    }
}

// ---------------- launch ----------------
extern "C" void kernel_launch(void* const* d_in, const int* in_sizes, int n_in,
                              void* d_out, int out_size) {
    const float* mag;
    const float* noise;
    if (in_sizes[0] == NBATCH*NFR*NBK) { mag = (const float*)d_in[0]; noise = (const float*)d_in[1]; }
    else                               { mag = (const float*)d_in[1]; noise = (const float*)d_in[0]; }
    float* out = (float*)d_out;

    k_mm_part<<<dim3(NCH, NBATCH), 64>>>(mag);
    k_filter_H<<<(NFQ + 127)/128, 128>>>();
    k_p1f<<<dim3(125, 2), 256>>>(noise);
    k_p2f<<<dim3(256, 2), 256>>>();
    k_pAi<<<dim3(256, 2), 256>>>();
    k_pBi<<<dim3(125, 2), 256>>>(out);
}

// round 5
// speedup vs baseline: 34.2651x; 1.1310x over previous
#include <cuda_runtime.h>
#include <math.h>

#define NSMP   256000        // = 512 * 500
#define N1     512
#define N2     500
#define NBATCH 4
#define NFR    500
#define NBK    64
#define NFQ    128001
#define NCH    10
#define CHF    50

// ---------------- scratch ----------------
__device__ float2 g_u[2][N1 * N2];     // 4 MB working buffer
__device__ float  g_H[NBATCH][NFQ];
__device__ float  g_part[NCH][NBATCH][NBK];

// ---------------- helpers ----------------
__device__ __forceinline__ float2 c_add(float2 a, float2 b){ return make_float2(a.x+b.x, a.y+b.y); }
__device__ __forceinline__ float2 c_sub(float2 a, float2 b){ return make_float2(a.x-b.x, a.y-b.y); }
__device__ __forceinline__ float2 cmul(float2 z, float cs, float sn) {
    return make_float2(z.x*cs - z.y*sn, z.x*sn + z.y*cs);
}

template<int R, bool INV>
__device__ __forceinline__ void butterfly(float2* v) {
    const float s = INV ? 1.f : -1.f;
    if constexpr (R == 4) {
        float2 t0 = c_add(v[0], v[2]), t1 = c_sub(v[0], v[2]);
        float2 t2 = c_add(v[1], v[3]), t3 = c_sub(v[1], v[3]);
        float2 it3 = make_float2(-s * t3.y, s * t3.x);
        v[0] = c_add(t0, t2); v[2] = c_sub(t0, t2);
        v[1] = c_add(t1, it3); v[3] = c_sub(t1, it3);
    } else if constexpr (R == 5) {
        const float c1 = 0.30901699437494742f, c2 = -0.80901699437494745f;
        const float s1 = 0.95105651629515357f, s2 =  0.58778525229247312f;
        float2 t1 = c_add(v[1], v[4]), t2 = c_add(v[2], v[3]);
        float2 t3 = c_sub(v[1], v[4]), t4 = c_sub(v[2], v[3]);
        float2 x0 = v[0];
        float2 m1 = make_float2(x0.x + c1*t1.x + c2*t2.x, x0.y + c1*t1.y + c2*t2.y);
        float2 m2 = make_float2(x0.x + c2*t1.x + c1*t2.x, x0.y + c2*t1.y + c1*t2.y);
        float2 u1 = make_float2(s1*t3.x + s2*t4.x, s1*t3.y + s2*t4.y);
        float2 u2 = make_float2(s2*t3.x - s1*t4.x, s2*t3.y - s1*t4.y);
        float2 iu1 = make_float2(-s*u1.y, s*u1.x);
        float2 iu2 = make_float2(-s*u2.y, s*u2.x);
        v[0] = make_float2(x0.x + t1.x + t2.x, x0.y + t1.y + t2.y);
        v[1] = c_add(m1, iu1); v[4] = c_sub(m1, iu1);
        v[2] = c_add(m2, iu2); v[3] = c_sub(m2, iu2);
    }
}

template<bool INV>
__device__ __forceinline__ void bfly8(float2* v) {
    float2 u0[4] = { v[0], v[2], v[4], v[6] };
    float2 u1[4] = { v[1], v[3], v[5], v[7] };
    butterfly<4, INV>(u0);
    butterfly<4, INV>(u1);
    const float h  = 0.70710678118654752f;
    const float si = INV ? 1.f : -1.f;
    float2 t0 = u1[0];
    float2 t1 = make_float2(h*(u1[1].x - si*u1[1].y), h*(si*u1[1].x + u1[1].y));
    float2 t2 = make_float2(-si*u1[2].y, si*u1[2].x);
    float2 t3 = make_float2(h*(-u1[3].x - si*u1[3].y), h*(si*u1[3].x - u1[3].y));
    v[0] = c_add(u0[0], t0); v[4] = c_sub(u0[0], t0);
    v[1] = c_add(u0[1], t1); v[5] = c_sub(u0[1], t1);
    v[2] = c_add(u0[2], t2); v[6] = c_sub(u0[2], t2);
    v[3] = c_add(u0[3], t3); v[7] = c_sub(u0[3], t3);
}

// ---------------- ping-pong FFT-500 stage bodies ----------------
template<bool INV>
__device__ __forceinline__ void f500_s1(const float2* __restrict__ src, float2* __restrict__ dst, int t) {
    if (t < 125) {
        float2 v[4];
#pragma unroll
        for (int r = 0; r < 4; r++) v[r] = src[t + 125*r];
        butterfly<4, INV>(v);
#pragma unroll
        for (int r = 0; r < 4; r++) dst[t*4 + r] = v[r];
    }
}
template<bool INV>
__device__ __forceinline__ void f500_s2(const float2* __restrict__ src, float2* __restrict__ dst, int t) {
    if (t < 100) {
        const float sg = INV ? 6.2831853071795864f : -6.2831853071795864f;
        float2 v[5]; int m = t & 3;
#pragma unroll
        for (int r = 0; r < 5; r++) v[r] = src[t + 100*r];
        float base = sg / 20.f * (float)m;
#pragma unroll
        for (int r = 1; r < 5; r++) { float sn, cs; __sincosf(base*r, &sn, &cs); v[r] = cmul(v[r], cs, sn); }
        butterfly<5, INV>(v);
        int db = (t >> 2)*20 + m;
#pragma unroll
        for (int r = 0; r < 5; r++) dst[db + 4*r] = v[r];
    }
}
template<bool INV>
__device__ __forceinline__ void f500_s3(const float2* __restrict__ src, float2* __restrict__ dst, int t) {
    if (t < 100) {
        const float sg = INV ? 6.2831853071795864f : -6.2831853071795864f;
        float2 v[5]; int m = t % 20;
#pragma unroll
        for (int r = 0; r < 5; r++) v[r] = src[t + 100*r];
        float base = sg / 100.f * (float)m;
#pragma unroll
        for (int r = 1; r < 5; r++) { float sn, cs; __sincosf(base*r, &sn, &cs); v[r] = cmul(v[r], cs, sn); }
        butterfly<5, INV>(v);
        int db = (t/20)*100 + m;
#pragma unroll
        for (int r = 0; r < 5; r++) dst[db + 20*r] = v[r];
    }
}
template<bool INV>
__device__ __forceinline__ void f500_s4(const float2* __restrict__ src, float2* __restrict__ dst, int t) {
    if (t < 100) {
        const float sg = INV ? 6.2831853071795864f : -6.2831853071795864f;
        float2 v[5];
#pragma unroll
        for (int r = 0; r < 5; r++) v[r] = src[t + 100*r];
        float base = sg / 500.f * (float)t;
#pragma unroll
        for (int r = 1; r < 5; r++) { float sn, cs; __sincosf(base*r, &sn, &cs); v[r] = cmul(v[r], cs, sn); }
        butterfly<5, INV>(v);
#pragma unroll
        for (int r = 0; r < 5; r++) dst[t + 100*r] = v[r];
    }
}

// ---------------- partial mean-magnitude (closed-form frame weights) ----------------
__global__ void k_mm_part(const float* __restrict__ mag) {
    int c = blockIdx.x, b = blockIdx.y;
    int t = threadIdx.x;    // 64
    __shared__ float sw[CHF];
    if (t < CHF) {
        int f = c*CHF + t;
        const double s = 499.0/255999.0;
        long long a1 = ((long long)f*255999LL + 498LL)/499LL;
        long long b1 = ((long long)(f+1)*255999LL + 498LL)/499LL - 1LL;
        if (b1 > 255999LL) b1 = 255999LL;
        double cnt1 = (double)(b1 - a1 + 1);
        double si1  = 0.5*(double)(a1 + b1)*cnt1;
        double sum  = cnt1*(double)(1 + f) - s*si1;
        if (f >= 1) {
            long long a2 = ((long long)(f-1)*255999LL + 498LL)/499LL;
            long long b2 = a1 - 1LL;
            if (b2 >= a2) {
                double cnt2 = (double)(b2 - a2 + 1);
                double si2  = 0.5*(double)(a2 + b2)*cnt2;
                sum += s*si2 - (double)(f-1)*cnt2;
            }
        }
        sw[t] = (float)(sum/256000.0);
    }
    __syncthreads();
    float acc = 0.f;
    const float* mp = mag + (b*NFR + c*CHF)*NBK + t;
#pragma unroll 10
    for (int f = 0; f < CHF; f++) acc += sw[f]*mp[f*NBK];
    g_part[c][b][t] = acc;
}

// ---------------- filter response H[b][f] ----------------
__global__ void __launch_bounds__(128) k_filter_H() {
    __shared__ float smm[NBATCH*NBK];
    int t = threadIdx.x;
    for (int i = t; i < NBATCH*NBK; i += 128) {
        float a = 0.f;
        const float* p = (const float*)g_part;
#pragma unroll
        for (int c = 0; c < NCH; c++) a += p[c*256 + i];
        smm[i] = a;
    }
    __syncthreads();

    int f = blockIdx.x*128 + t;
    if (f >= NFQ) return;

    const float la = logf(20.0f);
    const float d  = (logf(11025.0f) - la)/63.f;
    float freq = (float)f * (22050.0f/256000.0f);
    float xp = logf(freq + 1e-7f) - la;

    float te = __expf(-2.f*xp*xp);
    float to = te * __expf(4.f*d*xp - 2.f*d*d);
    float Re = __expf(8.f*d*xp - 8.f*d*d);
    float Ro = Re * __expf(-8.f*d*d);
    const float g4 = __expf(-16.f*d*d);

    float sum = 0.f, a0 = 0.f, a1 = 0.f, a2 = 0.f, a3 = 0.f;
#pragma unroll
    for (int k = 0; k < 64; k += 2) {
        sum += te + to;
        a0 += te*smm[k]       + to*smm[k+1];
        a1 += te*smm[64+k]    + to*smm[65+k];
        a2 += te*smm[128+k]   + to*smm[129+k];
        a3 += te*smm[192+k]   + to*smm[193+k];
        te *= Re; Re *= g4;
        to *= Ro; Ro *= g4;
    }
    float inv = 1.f/(sum + 1e-7f);
    g_H[0][f] = a0*inv; g_H[1][f] = a1*inv;
    g_H[2][f] = a2*inv; g_H[3][f] = a3*inv;
}

// ---------------- pass 1: FFT-512 per column + cross twiddle (pack fused) ----------------
__global__ void __launch_bounds__(256) k_p1f(const float* __restrict__ noise) {
    __shared__ float2 sm[4][516];
    int tid = threadIdx.x;
    int c = tid & 3, j = tid >> 2;
    int n2 = blockIdx.x*4 + c;
    int s = blockIdx.y;
    const float* n0r = noise + 2*s*NSMP;
    const float* n1r = noise + (2*s+1)*NSMP;

    float2 v[8];
#pragma unroll
    for (int r = 0; r < 8; r++) {
        int idx = (j + 64*r)*N2 + n2;
        v[r] = make_float2(n0r[idx], n1r[idx]);
    }
    bfly8<false>(v);
#pragma unroll
    for (int r = 0; r < 8; r++) sm[c][j*8 + r] = v[r];
    __syncthreads();
#pragma unroll
    for (int r = 0; r < 8; r++) v[r] = sm[c][j + 64*r];
    __syncthreads();
    {
        int m = j & 7;
        float base = -6.2831853071795864f/64.f * (float)m;
#pragma unroll
        for (int r = 1; r < 8; r++) { float sn, cs; __sincosf(base*r, &sn, &cs); v[r] = cmul(v[r], cs, sn); }
        bfly8<false>(v);
        int db = (j >> 3)*64 + m;
#pragma unroll
        for (int r = 0; r < 8; r++) sm[c][db + 8*r] = v[r];
    }
    __syncthreads();
#pragma unroll
    for (int r = 0; r < 8; r++) v[r] = sm[c][j + 64*r];
    {
        float base = -6.2831853071795864f/512.f * (float)j;
#pragma unroll
        for (int r = 1; r < 8; r++) { float sn, cs; __sincosf(base*r, &sn, &cs); v[r] = cmul(v[r], cs, sn); }
        bfly8<false>(v);
        float cb = -6.2831853071795864f/256000.f * (float)n2;
        float2* u = g_u[s];
#pragma unroll
        for (int r = 0; r < 8; r++) {
            int k1 = j + 64*r;
            float sn, cs; __sincosf(cb*(float)k1, &sn, &cs);
            u[k1*N2 + n2] = cmul(v[r], cs, sn);
        }
    }
}

// ---------------- fused middle pass: fwd FFT-500 + spectral filter + inv FFT-500 ----------------
// One block owns conjugate-pair rows {p, 512-p} (p=0: rows 0 and 256).
__global__ void __launch_bounds__(256) k_pMid() {
    __shared__ float2 sA[2][N2], sB[2][N2];
    int tid = threadIdx.x;
    int half = tid >> 7, t = tid & 127;
    int p = blockIdx.x;                  // 0..255
    int s = blockIdx.y;
    int ra = (p == 0) ? 0   : p;
    int rb = (p == 0) ? 256 : 512 - p;
    int myrow = half ? rb : ra;

    float2* R0 = sA[half];
    float2* R1 = sB[half];

    {   // load my row
        const float2* src = g_u[s] + myrow*N2;
        for (int i = t; i < N2; i += 128) R0[i] = src[i];
    }
    __syncthreads();

    // forward FFT-500 (ping-pong, 1 barrier per stage), spectrum ends in sA
    f500_s1<false>(R0, R1, t); __syncthreads();
    f500_s2<false>(R1, R0, t); __syncthreads();
    f500_s3<false>(R0, R1, t); __syncthreads();
    f500_s4<false>(R1, R0, t); __syncthreads();

    // spectral filter fused into inverse stage 1 (radix-4, Ns=1): sA -> sB
    const float* H0 = g_H[2*s];
    const float* H1 = g_H[2*s + 1];
    if (t < 125) {
        float2 v[4];
#pragma unroll
        for (int r = 0; r < 4; r++) {
            int k2 = t + 125*r;
            float2 zk = R0[k2];
            float2 zn;
            if (p == 0) {
                if (!half) zn = sA[0][k2 ? N2 - k2 : 0];   // row 0 self-paired
                else       zn = sA[1][N2 - 1 - k2];        // row 256 self-paired
            } else {
                zn = sA[1 - half][N2 - 1 - k2];            // cross pair k1 <-> 512-k1
            }
            int k  = myrow + (k2 << 9);
            int kh = (k <= 128000) ? k : 256000 - k;
            float h0 = H0[kh], h1 = H1[kh];
            float X0r = 0.5f*(zk.x + zn.x), X0i = 0.5f*(zk.y - zn.y);
            float X1r = 0.5f*(zk.y + zn.y), X1i = -0.5f*(zk.x - zn.x);
            v[r] = make_float2(h0*X0r - h1*X1i, h0*X0i + h1*X1r);
        }
        butterfly<4, true>(v);
#pragma unroll
        for (int r = 0; r < 4; r++) R1[t*4 + r] = v[r];
    }
    __syncthreads();

    f500_s2<true>(R1, R0, t); __syncthreads();
    f500_s3<true>(R0, R1, t); __syncthreads();

    // inverse stage 4 fused with cross-twiddle + store (output positions natural)
    if (t < 100) {
        float2 v[5];
#pragma unroll
        for (int r = 0; r < 5; r++) v[r] = R1[t + 100*r];
        float base = 6.2831853071795864f / 500.f * (float)t;
#pragma unroll
        for (int r = 1; r < 5; r++) { float sn, cs; __sincosf(base*r, &sn, &cs); v[r] = cmul(v[r], cs, sn); }
        butterfly<5, true>(v);
        float cb = 6.2831853071795864f/256000.f * (float)myrow;
        float2* dst = g_u[s] + myrow*N2;
#pragma unroll
        for (int r = 0; r < 5; r++) {
            int i = t + 100*r;
            float sn, cs; __sincosf(cb*(float)i, &sn, &cs);
            dst[i] = cmul(v[r], cs, sn);
        }
    }
}

// ---------------- pass B: iFFT-512 per column + scale + unpack ----------------
__global__ void __launch_bounds__(256) k_pBi(float* __restrict__ out) {
    __shared__ float2 sm[4][516];
    int tid = threadIdx.x;
    int c = tid & 3, j = tid >> 2;
    int n2 = blockIdx.x*4 + c;
    int s = blockIdx.y;
    const float2* u = g_u[s];

    float2 v[8];
#pragma unroll
    for (int r = 0; r < 8; r++) v[r] = u[(j + 64*r)*N2 + n2];
    bfly8<true>(v);
#pragma unroll
    for (int r = 0; r < 8; r++) sm[c][j*8 + r] = v[r];
    __syncthreads();
#pragma unroll
    for (int r = 0; r < 8; r++) v[r] = sm[c][j + 64*r];
    __syncthreads();
    {
        int m = j & 7;
        float base = 6.2831853071795864f/64.f * (float)m;
#pragma unroll
        for (int r = 1; r < 8; r++) { float sn, cs; __sincosf(base*r, &sn, &cs); v[r] = cmul(v[r], cs, sn); }
        bfly8<true>(v);
        int db = (j >> 3)*64 + m;
#pragma unroll
        for (int r = 0; r < 8; r++) sm[c][db + 8*r] = v[r];
    }
    __syncthreads();
#pragma unroll
    for (int r = 0; r < 8; r++) v[r] = sm[c][j + 64*r];
    {
        float base = 6.2831853071795864f/512.f * (float)j;
#pragma unroll
        for (int r = 1; r < 8; r++) { float sn, cs; __sincosf(base*r, &sn, &cs); v[r] = cmul(v[r], cs, sn); }
        bfly8<true>(v);
        const float sc = 1.f/256000.f;
        float* o0 = out + 2*s*NSMP;
        float* o1 = out + (2*s+1)*NSMP;
#pragma unroll
        for (int r = 0; r < 8; r++) {
            int idx = (j + 64*r)*N2 + n2;
            o0[idx] = v[r].x * sc;
            o1[idx] = v[r].y * sc;
        }
    }
}

// ---------------- launch ----------------
extern "C" void kernel_launch(void* const* d_in, const int* in_sizes, int n_in,
                              void* d_out, int out_size) {
    const float* mag;
    const float* noise;
    if (in_sizes[0] == NBATCH*NFR*NBK) { mag = (const float*)d_in[0]; noise = (const float*)d_in[1]; }
    else                               { mag = (const float*)d_in[1]; noise = (const float*)d_in[0]; }
    float* out = (float*)d_out;

    k_mm_part<<<dim3(NCH, NBATCH), 64>>>(mag);
    k_filter_H<<<(NFQ + 127)/128, 128>>>();
    k_p1f<<<dim3(125, 2), 256>>>(noise);
    k_pMid<<<dim3(256, 2), 256>>>();
    k_pBi<<<dim3(125, 2), 256>>>(out);
}

// round 6
// speedup vs baseline: 36.1436x; 1.0548x over previous
#include <cuda_runtime.h>
#include <math.h>

#define NSMP   256000        // = 512 * 500
#define N1     512
#define N2     500
#define NBATCH 4
#define NFR    500
#define NBK    64
#define NFQ    128001
#define NCH    10
#define CHF    50

// ---------------- scratch ----------------
__device__ float2 g_u[2][N1 * N2];     // 4 MB working buffer
__device__ float  g_H[NBATCH][NFQ];
__device__ float  g_part[NCH][NBATCH][NBK];

// ---------------- helpers ----------------
__device__ __forceinline__ float2 c_add(float2 a, float2 b){ return make_float2(a.x+b.x, a.y+b.y); }
__device__ __forceinline__ float2 c_sub(float2 a, float2 b){ return make_float2(a.x-b.x, a.y-b.y); }
__device__ __forceinline__ float2 cxm(float2 a, float2 b){
    return make_float2(a.x*b.x - a.y*b.y, a.x*b.y + a.y*b.x);
}

template<int R, bool INV>
__device__ __forceinline__ void butterfly(float2* v) {
    const float s = INV ? 1.f : -1.f;
    if constexpr (R == 4) {
        float2 t0 = c_add(v[0], v[2]), t1 = c_sub(v[0], v[2]);
        float2 t2 = c_add(v[1], v[3]), t3 = c_sub(v[1], v[3]);
        float2 it3 = make_float2(-s * t3.y, s * t3.x);
        v[0] = c_add(t0, t2); v[2] = c_sub(t0, t2);
        v[1] = c_add(t1, it3); v[3] = c_sub(t1, it3);
    } else if constexpr (R == 5) {
        const float c1 = 0.30901699437494742f, c2 = -0.80901699437494745f;
        const float s1 = 0.95105651629515357f, s2 =  0.58778525229247312f;
        float2 t1 = c_add(v[1], v[4]), t2 = c_add(v[2], v[3]);
        float2 t3 = c_sub(v[1], v[4]), t4 = c_sub(v[2], v[3]);
        float2 x0 = v[0];
        float2 m1 = make_float2(x0.x + c1*t1.x + c2*t2.x, x0.y + c1*t1.y + c2*t2.y);
        float2 m2 = make_float2(x0.x + c2*t1.x + c1*t2.x, x0.y + c2*t1.y + c1*t2.y);
        float2 u1 = make_float2(s1*t3.x + s2*t4.x, s1*t3.y + s2*t4.y);
        float2 u2 = make_float2(s2*t3.x - s1*t4.x, s2*t3.y - s1*t4.y);
        float2 iu1 = make_float2(-s*u1.y, s*u1.x);
        float2 iu2 = make_float2(-s*u2.y, s*u2.x);
        v[0] = make_float2(x0.x + t1.x + t2.x, x0.y + t1.y + t2.y);
        v[1] = c_add(m1, iu1); v[4] = c_sub(m1, iu1);
        v[2] = c_add(m2, iu2); v[3] = c_sub(m2, iu2);
    }
}

template<bool INV>
__device__ __forceinline__ void bfly8(float2* v) {
    float2 u0[4] = { v[0], v[2], v[4], v[6] };
    float2 u1[4] = { v[1], v[3], v[5], v[7] };
    butterfly<4, INV>(u0);
    butterfly<4, INV>(u1);
    const float h  = 0.70710678118654752f;
    const float si = INV ? 1.f : -1.f;
    float2 t0 = u1[0];
    float2 t1 = make_float2(h*(u1[1].x - si*u1[1].y), h*(si*u1[1].x + u1[1].y));
    float2 t2 = make_float2(-si*u1[2].y, si*u1[2].x);
    float2 t3 = make_float2(h*(-u1[3].x - si*u1[3].y), h*(si*u1[3].x - u1[3].y));
    v[0] = c_add(u0[0], t0); v[4] = c_sub(u0[0], t0);
    v[1] = c_add(u0[1], t1); v[5] = c_sub(u0[1], t1);
    v[2] = c_add(u0[2], t2); v[6] = c_sub(u0[2], t2);
    v[3] = c_add(u0[3], t3); v[7] = c_sub(u0[3], t3);
}

// one sincosf + power chain: multiply v[1..4] by w^r
__device__ __forceinline__ void tw5(float base, float2* v) {
    float sn, cs; __sincosf(base, &sn, &cs);
    float2 w1 = make_float2(cs, sn);
    float2 w2 = cxm(w1, w1);
    float2 w3 = cxm(w2, w1);
    float2 w4 = cxm(w2, w2);
    v[1] = cxm(v[1], w1); v[2] = cxm(v[2], w2);
    v[3] = cxm(v[3], w3); v[4] = cxm(v[4], w4);
}

// one sincosf + power chain: multiply v[1..7] by w^r
__device__ __forceinline__ void tw8(float base, float2* v) {
    float sn, cs; __sincosf(base, &sn, &cs);
    float2 w1 = make_float2(cs, sn);
    float2 w2 = cxm(w1, w1);
    float2 w3 = cxm(w2, w1);
    float2 w4 = cxm(w2, w2);
    float2 w5 = cxm(w4, w1);
    float2 w6 = cxm(w3, w3);
    float2 w7 = cxm(w3, w4);
    v[1] = cxm(v[1], w1); v[2] = cxm(v[2], w2); v[3] = cxm(v[3], w3);
    v[4] = cxm(v[4], w4); v[5] = cxm(v[5], w5); v[6] = cxm(v[6], w6);
    v[7] = cxm(v[7], w7);
}

// radix-5 Stockham stage body (caller guards t<100)
template<bool INV>
__device__ __forceinline__ void stage5(const float2* __restrict__ src, float2* __restrict__ dst,
                                       int t, int m, int Ns, float base) {
    float2 v[5];
#pragma unroll
    for (int r = 0; r < 5; r++) v[r] = src[t + 100*r];
    tw5(base, v);
    butterfly<5, INV>(v);
    int db = (t/Ns)*(Ns*5) + m;
#pragma unroll
    for (int r = 0; r < 5; r++) dst[db + Ns*r] = v[r];
}

#define BROW() asm volatile("bar.sync %0, 128;" :: "r"(half + 1) : "memory")

// ---------------- partial mean-magnitude (closed-form frame weights) ----------------
__global__ void k_mm_part(const float* __restrict__ mag) {
    int c = blockIdx.x, b = blockIdx.y;
    int t = threadIdx.x;    // 64
    __shared__ float sw[CHF];
    if (t < CHF) {
        int f = c*CHF + t;
        const double s = 499.0/255999.0;
        long long a1 = ((long long)f*255999LL + 498LL)/499LL;
        long long b1 = ((long long)(f+1)*255999LL + 498LL)/499LL - 1LL;
        if (b1 > 255999LL) b1 = 255999LL;
        double cnt1 = (double)(b1 - a1 + 1);
        double si1  = 0.5*(double)(a1 + b1)*cnt1;
        double sum  = cnt1*(double)(1 + f) - s*si1;
        if (f >= 1) {
            long long a2 = ((long long)(f-1)*255999LL + 498LL)/499LL;
            long long b2 = a1 - 1LL;
            if (b2 >= a2) {
                double cnt2 = (double)(b2 - a2 + 1);
                double si2  = 0.5*(double)(a2 + b2)*cnt2;
                sum += s*si2 - (double)(f-1)*cnt2;
            }
        }
        sw[t] = (float)(sum/256000.0);
    }
    __syncthreads();
    float acc = 0.f;
    const float* mp = mag + (b*NFR + c*CHF)*NBK + t;
#pragma unroll 10
    for (int f = 0; f < CHF; f++) acc += sw[f]*mp[f*NBK];
    g_part[c][b][t] = acc;
}

// ---------------- filter response H[b][f] ----------------
__global__ void __launch_bounds__(128) k_filter_H() {
    __shared__ float smm[NBATCH*NBK];
    int t = threadIdx.x;
    for (int i = t; i < NBATCH*NBK; i += 128) {
        float a = 0.f;
        const float* p = (const float*)g_part;
#pragma unroll
        for (int c = 0; c < NCH; c++) a += p[c*256 + i];
        smm[i] = a;
    }
    __syncthreads();

    int f = blockIdx.x*128 + t;
    if (f >= NFQ) return;

    const float la = 2.99573227355399f;                 // log(20)
    const float d  = (__logf(11025.0f) - la)/63.f;
    float freq = (float)f * (22050.0f/256000.0f);
    float xp = __logf(freq + 1e-7f) - la;

    float te = __expf(-2.f*xp*xp);
    float to = te * __expf(4.f*d*xp - 2.f*d*d);
    float Re = __expf(8.f*d*xp - 8.f*d*d);
    float Ro = Re * __expf(-8.f*d*d);
    const float g4 = __expf(-16.f*d*d);

    float sum = 0.f, a0 = 0.f, a1 = 0.f, a2 = 0.f, a3 = 0.f;
#pragma unroll
    for (int k = 0; k < 64; k += 2) {
        sum += te + to;
        a0 += te*smm[k]       + to*smm[k+1];
        a1 += te*smm[64+k]    + to*smm[65+k];
        a2 += te*smm[128+k]   + to*smm[129+k];
        a3 += te*smm[192+k]   + to*smm[193+k];
        te *= Re; Re *= g4;
        to *= Ro; Ro *= g4;
    }
    float inv = 1.f/(sum + 1e-7f);
    g_H[0][f] = a0*inv; g_H[1][f] = a1*inv;
    g_H[2][f] = a2*inv; g_H[3][f] = a3*inv;
}

// ---------------- pass 1: FFT-512 per column + cross twiddle (8 cols/block) ----------------
__global__ void __launch_bounds__(512) k_p1f(const float* __restrict__ noise) {
    __shared__ float2 sm[8][516];
    int tid = threadIdx.x;
    int c = tid & 7, j = tid >> 3;          // j in [0,64)
    int n2 = blockIdx.x*8 + c;
    bool val = (n2 < N2);
    int s = blockIdx.y;
    const float* n0r = noise + 2*s*NSMP;
    const float* n1r = noise + (2*s+1)*NSMP;

    float2 v[8];
    if (val) {
#pragma unroll
        for (int r = 0; r < 8; r++) {
            int idx = (j + 64*r)*N2 + n2;
            v[r] = make_float2(n0r[idx], n1r[idx]);
        }
    } else {
#pragma unroll
        for (int r = 0; r < 8; r++) v[r] = make_float2(0.f, 0.f);
    }
    bfly8<false>(v);
#pragma unroll
    for (int r = 0; r < 8; r++) sm[c][j*8 + r] = v[r];
    __syncthreads();
#pragma unroll
    for (int r = 0; r < 8; r++) v[r] = sm[c][j + 64*r];
    __syncthreads();
    {
        int m = j & 7;
        tw8(-6.2831853071795864f/64.f * (float)m, v);
        bfly8<false>(v);
        int db = (j >> 3)*64 + m;
#pragma unroll
        for (int r = 0; r < 8; r++) sm[c][db + 8*r] = v[r];
    }
    __syncthreads();
#pragma unroll
    for (int r = 0; r < 8; r++) v[r] = sm[c][j + 64*r];
    {
        tw8(-6.2831853071795864f/512.f * (float)j, v);
        bfly8<false>(v);
        if (val) {
            float cb = -6.2831853071795864f/256000.f * (float)n2;
            float snj, csj; __sincosf(cb*(float)j, &snj, &csj);
            float snW, csW; __sincosf(cb*64.f, &snW, &csW);
            float2 wk = make_float2(csj, snj);
            float2 W  = make_float2(csW, snW);
            float2* u = g_u[s];
#pragma unroll
            for (int r = 0; r < 8; r++) {
                int k1 = j + 64*r;
                u[k1*N2 + n2] = cxm(v[r], wk);
                wk = cxm(wk, W);
            }
        }
    }
}

// ---------------- fused middle: fwd FFT-500 + spectral filter + inv FFT-500 ----------------
__global__ void __launch_bounds__(256) k_pMid() {
    __shared__ float2 sA[2][N2], sB[2][N2];
    int tid = threadIdx.x;
    int half = tid >> 7, t = tid & 127;
    int p = blockIdx.x;                  // 0..255
    int s = blockIdx.y;
    int ra = (p == 0) ? 0   : p;
    int rb = (p == 0) ? 256 : 512 - p;
    int myrow = half ? rb : ra;
    float2* A = sA[half];
    float2* B = sB[half];

    // fwd s1: radix-4, Ns=1 — read g_u directly
    {
        const float2* src = g_u[s] + myrow*N2;
        if (t < 125) {
            float2 v[4];
#pragma unroll
            for (int r = 0; r < 4; r++) v[r] = src[t + 125*r];
            butterfly<4, false>(v);
#pragma unroll
            for (int r = 0; r < 4; r++) A[t*4 + r] = v[r];
        }
    }
    BROW();
    if (t < 100) stage5<false>(A, B, t, t & 3,  4,  -6.2831853071795864f/20.f  * (float)(t & 3));
    BROW();
    if (t < 100) stage5<false>(B, A, t, t % 20, 20, -6.2831853071795864f/100.f * (float)(t % 20));
    BROW();
    if (t < 100) stage5<false>(A, B, t, t,      100,-6.2831853071795864f/500.f * (float)t);
    __syncthreads();    // spectrum in sB (both halves)

    // spectral filter fused into inverse s1 (radix-4, Ns=1): sB -> sA
    {
        const float* H0 = g_H[2*s];
        const float* H1 = g_H[2*s + 1];
        if (t < 125) {
            float2 v[4];
#pragma unroll
            for (int r = 0; r < 4; r++) {
                int k2 = t + 125*r;
                float2 zk = B[k2];
                float2 zn;
                if (p == 0) {
                    if (!half) zn = sB[0][k2 ? N2 - k2 : 0];
                    else       zn = sB[1][N2 - 1 - k2];
                } else {
                    zn = sB[1 - half][N2 - 1 - k2];
                }
                int k  = myrow + (k2 << 9);
                int kh = (k <= 128000) ? k : 256000 - k;
                float h0 = H0[kh], h1 = H1[kh];
                float X0r = 0.5f*(zk.x + zn.x), X0i = 0.5f*(zk.y - zn.y);
                float X1r = 0.5f*(zk.y + zn.y), X1i = -0.5f*(zk.x - zn.x);
                v[r] = make_float2(h0*X0r - h1*X1i, h0*X0i + h1*X1r);
            }
            butterfly<4, true>(v);
#pragma unroll
            for (int r = 0; r < 4; r++) A[t*4 + r] = v[r];
        }
    }
    __syncthreads();    // cross-half sB reads must finish before inv writes sB

    if (t < 100) stage5<true>(A, B, t, t & 3,  4,  6.2831853071795864f/20.f  * (float)(t & 3));
    BROW();
    if (t < 100) stage5<true>(B, A, t, t % 20, 20, 6.2831853071795864f/100.f * (float)(t % 20));
    BROW();
    // inv s4 (Ns=100) fused with cross-twiddle + store
    if (t < 100) {
        float2 v[5];
#pragma unroll
        for (int r = 0; r < 5; r++) v[r] = A[t + 100*r];
        tw5(6.2831853071795864f/500.f * (float)t, v);
        butterfly<5, true>(v);
        float cb = 6.2831853071795864f/256000.f * (float)myrow;
        float snt, cst; __sincosf(cb*(float)t,   &snt, &cst);
        float snW, csW; __sincosf(cb*100.f,      &snW, &csW);
        float2 wk = make_float2(cst, snt);
        float2 W  = make_float2(csW, snW);
        float2* dst = g_u[s] + myrow*N2;
#pragma unroll
        for (int r = 0; r < 5; r++) {
            dst[t + 100*r] = cxm(v[r], wk);
            wk = cxm(wk, W);
        }
    }
}

// ---------------- pass B: iFFT-512 per column + scale + unpack (8 cols/block) ----------------
__global__ void __launch_bounds__(512) k_pBi(float* __restrict__ out) {
    __shared__ float2 sm[8][516];
    int tid = threadIdx.x;
    int c = tid & 7, j = tid >> 3;
    int n2 = blockIdx.x*8 + c;
    bool val = (n2 < N2);
    int s = blockIdx.y;
    const float2* u = g_u[s];

    float2 v[8];
    if (val) {
#pragma unroll
        for (int r = 0; r < 8; r++) v[r] = u[(j + 64*r)*N2 + n2];
    } else {
#pragma unroll
        for (int r = 0; r < 8; r++) v[r] = make_float2(0.f, 0.f);
    }
    bfly8<true>(v);
#pragma unroll
    for (int r = 0; r < 8; r++) sm[c][j*8 + r] = v[r];
    __syncthreads();
#pragma unroll
    for (int r = 0; r < 8; r++) v[r] = sm[c][j + 64*r];
    __syncthreads();
    {
        int m = j & 7;
        tw8(6.2831853071795864f/64.f * (float)m, v);
        bfly8<true>(v);
        int db = (j >> 3)*64 + m;
#pragma unroll
        for (int r = 0; r < 8; r++) sm[c][db + 8*r] = v[r];
    }
    __syncthreads();
#pragma unroll
    for (int r = 0; r < 8; r++) v[r] = sm[c][j + 64*r];
    {
        tw8(6.2831853071795864f/512.f * (float)j, v);
        bfly8<true>(v);
        if (val) {
            const float sc = 1.f/256000.f;
            float* o0 = out + 2*s*NSMP;
            float* o1 = out + (2*s+1)*NSMP;
#pragma unroll
            for (int r = 0; r < 8; r++) {
                int idx = (j + 64*r)*N2 + n2;
                o0[idx] = v[r].x * sc;
                o1[idx] = v[r].y * sc;
            }
        }
    }
}

// ---------------- launch ----------------
extern "C" void kernel_launch(void* const* d_in, const int* in_sizes, int n_in,
                              void* d_out, int out_size) {
    const float* mag;
    const float* noise;
    if (in_sizes[0] == NBATCH*NFR*NBK) { mag = (const float*)d_in[0]; noise = (const float*)d_in[1]; }
    else                               { mag = (const float*)d_in[1]; noise = (const float*)d_in[0]; }
    float* out = (float*)d_out;

    k_mm_part<<<dim3(NCH, NBATCH), 64>>>(mag);
    k_filter_H<<<(NFQ + 127)/128, 128>>>();
    k_p1f<<<dim3(63, 2), 512>>>(noise);
    k_pMid<<<dim3(256, 2), 256>>>();
    k_pBi<<<dim3(63, 2), 512>>>(out);
}